// round 16
// baseline (speedup 1.0000x reference)
#include <cuda_runtime.h>
#include <cuda_bf16.h>
#include <cstdint>
#include <cstddef>

#define VOCAB 2048
#define EMB 256
#define KTOT 2304          // EMB + VOCAB
#define NTOT 8192          // 4*VOCAB
#define BATCH 32
#define TSTEPS 8
#define LAT 128

#define NBLK 128           // persistent blocks; each owns 16 h-cols (x4 gates)
#define THREADS 288        // 8 compute warps (nq2 x kg4) + 1 producer warp
#define KTILE 192
#define NITER (KTOT / KTILE)   // 12
#define NITER1 2               // t==1: h==0; tiles 0,1 cover k<384 (h rows are 0)
#define STAGES 3
#define WPITCH 72              // bf16 elems per W row (64 + 8 pad)  [baked into gmem]
#define WSTAGE (KTILE * WPITCH)            // 13,824 elems
#define WTILE_BYTES (WSTAGE * 2)           // 27,648 B, contiguous in gmem
#define APITCH 2312            // bf16 elems per A row (2304 + 8 pad) [gmem AND smem]
#define AROW32 (32 * APITCH)               // 73,984 elems
#define ACHUNK_B (KTILE * 2)               // 384 B per A row-slice per tile
#define TILE_TX (WTILE_BYTES + 32 * ACHUNK_B)   // 39,936 B per tile barrier
#define GPITCH 66              // float pitch per gate-staging buffer (aliases Asm)
#define SMEM_BYTES ((AROW32 + STAGES * WSTAGE) * 2)        // 230,912 B

#define CONV_BLOCKS 256
#define CONV_THREADS 512

// ---------------- device scratch (no allocations allowed) -------------------
__device__ __align__(16) __nv_bfloat16 g_W[(size_t)NBLK * KTOT * WPITCH];  // 42.5MB
__device__ __align__(16) __nv_bfloat16 g_Abf[2][AROW32];   // ping-pong [emb|h] padded
__device__ float g_c[BATCH * VOCAB];
__device__ float g_h[BATCH * VOCAB];
__device__ float g_partZ[2][BATCH * NBLK];                  // ping-pong
__device__ float g_partS[2][BATCH * NBLK];
__device__ unsigned g_bar_cnt = 0;     // monotonic ticket counter (never reset)

// ---------------- helpers ----------------------------------------------------
__device__ __forceinline__ uint32_t smem_u32(const void* p) {
    return (uint32_t)__cvta_generic_to_shared(p);
}
__device__ __forceinline__ void mbar_init(uint32_t addr, uint32_t count) {
    asm volatile("mbarrier.init.shared.b64 [%0], %1;\n" :: "r"(addr), "r"(count) : "memory");
}
__device__ __forceinline__ void mbar_expect_tx(uint32_t addr, uint32_t bytes) {
    asm volatile("mbarrier.arrive.expect_tx.shared.b64 _, [%0], %1;\n"
                 :: "r"(addr), "r"(bytes) : "memory");
}
__device__ __forceinline__ void mbar_arrive(uint32_t addr) {
    asm volatile("mbarrier.arrive.shared.b64 _, [%0];\n" :: "r"(addr) : "memory");
}
__device__ __forceinline__ void bulk_g2s(uint32_t dst, const void* src,
                                         uint32_t bytes, uint32_t mbar) {
    asm volatile("cp.async.bulk.shared::cta.global.mbarrier::complete_tx::bytes "
                 "[%0], [%1], %2, [%3];\n"
                 :: "r"(dst), "l"(src), "r"(bytes), "r"(mbar) : "memory");
}
__device__ __forceinline__ void mbar_wait(uint32_t addr, uint32_t phase) {
    asm volatile("{\n\t.reg .pred p;\n"
                 "WAITLOOP%=:\n\t"
                 "mbarrier.try_wait.parity.shared.b64 p, [%0], %1;\n\t"
                 "@!p bra WAITLOOP%=;\n\t}"
                 :: "r"(addr), "r"(phase) : "memory");
}
__device__ __forceinline__ void ldsm_x4(uint32_t* r, uint32_t addr) {
    asm volatile("ldmatrix.sync.aligned.m8n8.x4.shared.b16 {%0,%1,%2,%3}, [%4];\n"
                 : "=r"(r[0]), "=r"(r[1]), "=r"(r[2]), "=r"(r[3]) : "r"(addr));
}
__device__ __forceinline__ void ldsm_x4_t(uint32_t* r, uint32_t addr) {
    asm volatile("ldmatrix.sync.aligned.m8n8.x4.trans.shared.b16 {%0,%1,%2,%3}, [%4];\n"
                 : "=r"(r[0]), "=r"(r[1]), "=r"(r[2]), "=r"(r[3]) : "r"(addr));
}
__device__ __forceinline__ void mma16816(float* d, const uint32_t* a, uint32_t b0, uint32_t b1) {
    asm volatile("mma.sync.aligned.m16n8k16.row.col.f32.bf16.bf16.f32 "
                 "{%0,%1,%2,%3}, {%4,%5,%6,%7}, {%8,%9}, {%0,%1,%2,%3};\n"
                 : "+f"(d[0]), "+f"(d[1]), "+f"(d[2]), "+f"(d[3])
                 : "r"(a[0]), "r"(a[1]), "r"(a[2]), "r"(a[3]), "r"(b0), "r"(b1));
}
__device__ __forceinline__ float fsig(float x)  { return __fdividef(1.f, 1.f + __expf(-x)); }
__device__ __forceinline__ float ftanh(float x) { return __fdividef(2.f, 1.f + __expf(-2.f * x)) - 1.f; }

__device__ __forceinline__ void cvt8(const float* __restrict__ src,
                                     __nv_bfloat16* __restrict__ dst) {
    float4 f0 = reinterpret_cast<const float4*>(src)[0];
    float4 f1 = reinterpret_cast<const float4*>(src)[1];
    __nv_bfloat162 b0 = __float22bfloat162_rn(make_float2(f0.x, f0.y));
    __nv_bfloat162 b1 = __float22bfloat162_rn(make_float2(f0.z, f0.w));
    __nv_bfloat162 b2 = __float22bfloat162_rn(make_float2(f1.x, f1.y));
    __nv_bfloat162 b3 = __float22bfloat162_rn(make_float2(f1.z, f1.w));
    uint4 pv;
    pv.x = *reinterpret_cast<unsigned*>(&b0);
    pv.y = *reinterpret_cast<unsigned*>(&b1);
    pv.z = *reinterpret_cast<unsigned*>(&b2);
    pv.w = *reinterpret_cast<unsigned*>(&b3);
    *reinterpret_cast<uint4*>(dst) = pv;
}

// Reset-free monotonic grid barrier (L2 atomics only; proven in R8).
__device__ __forceinline__ void grid_sync() {
    __syncthreads();
    if (threadIdx.x == 0) {
        __threadfence();                               // release prior stores
        unsigned ticket = atomicAdd(&g_bar_cnt, 1u);
        unsigned target = ticket - (ticket % NBLK) + NBLK;
        while (atomicAdd(&g_bar_cnt, 0u) < target) __nanosleep(64);
        __threadfence();                               // acquire others' stores
    }
    __syncthreads();
}

// ---------------- kernel 1: convert + repack (coalesced READS) --------------
__global__ __launch_bounds__(CONV_THREADS, 2) void convert_kernel(
    const float* __restrict__ Wi, const float* __restrict__ Wh,
    const float* __restrict__ E, const int* __restrict__ tokens,
    float* __restrict__ out)
{
    const int gid = blockIdx.x * CONV_THREADS + threadIdx.x;   // 0..131071
#pragma unroll
    for (int i = 0; i < 18; ++i) {                // 2,359,296 W chunks total
        int c = gid + i * (CONV_BLOCKS * CONV_THREADS);
        int k = c >> 10, cpos = c & 1023;
        int g = cpos >> 8, blkd = (cpos & 255) >> 1, half = cpos & 1;
        const float* src = ((k < EMB) ? (Wi + (size_t)k * NTOT)
                                      : (Wh + (size_t)(k - EMB) * NTOT)) + cpos * 8;
        cvt8(src, g_W + ((size_t)blkd * KTOT + k) * WPITCH + g * 16 + half * 8);
    }
    if (gid < BATCH * VOCAB) {                    // 65,536: fp32 state init
        g_c[gid] = 0.f;
        g_h[gid] = 0.f;
    }
    if (gid < AROW32) {                           // 73,984: A buffers for step 1
        int r = gid / APITCH, p = gid % APITCH;
        float v = 0.f;
        if (p < EMB) v = E[(size_t)tokens[r * TSTEPS] * EMB + p];   // token col 1
        g_Abf[0][gid] = __float2bfloat16(v);      // emb | h=0 | pad=0
        g_Abf[1][gid] = __float2bfloat16(0.f);
    }
    if (blockIdx.x == CONV_BLOCKS - 1) {          // out[:,0,:] = 0 (exact)
#pragma unroll
        for (int j = 0; j < 8; ++j) {
            int idx = threadIdx.x + j * CONV_THREADS;   // 0..4095
            out[((size_t)(idx >> 7) * TSTEPS) * LAT + (idx & 127)] = 0.f;
        }
    }
}

// ---------------- kernel 2: persistent step loop -----------------------------
// Continuous tile stream: global tile index j over all steps; mbarriers are
// initialized ONCE and phases flow as (j/STAGES)&1. Each tile's barrier covers
// the W tile (lane0 bulk) AND 32 A row-slices (one per producer lane).
__global__ __launch_bounds__(THREADS, 1) void persistent_kernel(
    const int* __restrict__ tokens, const float* __restrict__ bias,
    const float* __restrict__ E, float* __restrict__ out)
{
    extern __shared__ __align__(16) char dynsmem[];
    __nv_bfloat16* Asm = reinterpret_cast<__nv_bfloat16*>(dynsmem);   // 32 x APITCH
    __nv_bfloat16* Wsm = Asm + AROW32;                                 // STAGES x WSTAGE
    float* gsm = reinterpret_cast<float*>(Asm);     // 4 x 32*GPITCH floats (alias)
    __shared__ float bsm[64];
    __shared__ float redz[4], reds[4];
    __shared__ int tsm[32];
    __shared__ __align__(8) uint64_t m_full[STAGES];
    __shared__ __align__(8) uint64_t m_empty[STAGES];

    const int blk  = blockIdx.x;
    const int tid  = threadIdx.x;
    const int lane = tid & 31, warp = tid >> 5;      // warps 0..8
    const int nq = warp & 1;          // n half: W cols nq*32..+32
    const int kg = warp >> 1;         // k-group 0..3: ks = kg*3 + {0,1,2}

    if (tid < 64)
        bsm[tid] = bias[(tid >> 4) * 2048 + blk * 16 + (tid & 15)];
    if (tid == 0) {                   // init ONCE; phases continue globally
#pragma unroll
        for (int s = 0; s < STAGES; ++s) {
            mbar_init(smem_u32(&m_full[s]), 1);
            mbar_init(smem_u32(&m_empty[s]), 8);    // 8 compute warps
        }
    }
    __syncthreads();

    const __nv_bfloat16* wblk = g_W + (size_t)blk * KTOT * WPITCH;
    int jglob = 0;   // global tile counter (74 total)

    for (int t = 1; t < TSTEPS; ++t) {
        const int nit = (t == 1) ? NITER1 : NITER;

        if (tid < 32) tsm[tid] = tokens[tid * TSTEPS + (t - 1)];

        float acc[2][4][4];     // [mh][n8 chunk][frag]
#pragma unroll
        for (int i = 0; i < 2; i++)
#pragma unroll
            for (int j = 0; j < 4; j++)
#pragma unroll
                for (int f = 0; f < 4; f++) acc[i][j][f] = 0.f;

        if (warp == 8) {
            // ---------- producer warp: W bulk (lane0) + A slices (all lanes) --
            const __nv_bfloat16* abf = g_Abf[(t - 1) & 1];
            for (int it = 0; it < nit; ++it) {
                const int j = jglob + it;
                const int st = j % STAGES;
                if (lane == 0) {
                    if (j >= STAGES)
                        mbar_wait(smem_u32(&m_empty[st]), ((j / STAGES) - 1) & 1);
                    mbar_expect_tx(smem_u32(&m_full[st]), TILE_TX);
                }
                __syncwarp();
                if (lane == 0)
                    bulk_g2s(smem_u32(&Wsm[st * WSTAGE]),
                             wblk + (size_t)it * KTILE * WPITCH,
                             WTILE_BYTES, smem_u32(&m_full[st]));
                // A row-slice: lane r -> rows r, cols [it*KTILE, +KTILE)
                bulk_g2s(smem_u32(&Asm[lane * APITCH + it * KTILE]),
                         abf + (size_t)lane * APITCH + it * KTILE,
                         ACHUNK_B, smem_u32(&m_full[st]));
            }
        } else {
            // ---------- compute warps (8): M=32 x N=32 per warp --------------
            for (int it = 0; it < nit; ++it) {
                const int j = jglob + it;
                const int st = j % STAGES;
                mbar_wait(smem_u32(&m_full[st]), (j / STAGES) & 1);
                const __nv_bfloat16* ws = Wsm + st * WSTAGE;
                const int kbase = it * KTILE;
#pragma unroll
                for (int k2 = 0; k2 < 3; ++k2) {
                    const int ks = kg * 3 + k2;
                    const int acol = kbase + ks * 16 + (lane >> 4) * 8;
                    uint32_t a0[4], a1[4];
                    ldsm_x4(a0, smem_u32(&Asm[(lane & 15) * APITCH + acol]));
                    ldsm_x4(a1, smem_u32(&Asm[(16 + (lane & 15)) * APITCH + acol]));
                    const int krow = ks * 16 + (lane & 15);
#pragma unroll
                    for (int nsub = 0; nsub < 2; ++nsub) {
                        uint32_t bq[4];
                        int col = nq * 32 + nsub * 16 + (lane >> 4) * 8;
                        ldsm_x4_t(bq, smem_u32(&ws[krow * WPITCH + col]));
                        mma16816(acc[0][nsub * 2 + 0], a0, bq[0], bq[1]);
                        mma16816(acc[0][nsub * 2 + 1], a0, bq[2], bq[3]);
                        mma16816(acc[1][nsub * 2 + 0], a1, bq[0], bq[1]);
                        mma16816(acc[1][nsub * 2 + 1], a1, bq[2], bq[3]);
                    }
                }
                if (lane == 0) mbar_arrive(smem_u32(&m_empty[st]));
            }
        }
        jglob += nit;
        __syncthreads();        // [sync 1] all mainloop smem reads done (gsm alias)

        // ---------- epilogue: each warp stores to its own kg buffer ----------
        if (warp < 8) {
            float* gb = gsm + kg * (32 * GPITCH);
#pragma unroll
            for (int mhh = 0; mhh < 2; ++mhh)
#pragma unroll
                for (int nj = 0; nj < 4; ++nj) {
                    int row = mhh * 16 + (lane >> 2);
                    int col = nq * 32 + nj * 8 + (lane & 3) * 2;
                    *reinterpret_cast<float2*>(&gb[row * GPITCH + col]) =
                        make_float2(acc[mhh][nj][0], acc[mhh][nj][1]);
                    *reinterpret_cast<float2*>(&gb[(row + 8) * GPITCH + col]) =
                        make_float2(acc[mhh][nj][2], acc[mhh][nj][3]);
                }
        }
        __syncthreads();        // [sync 2] all 4 partial buffers ready

        // ---------- LSTM pointwise + partials + next-step A build ------------
        if (tid < 256) {
#pragma unroll
            for (int half = 0; half < 2; ++half) {
                int e = tid + half * 256;          // 0..511
                int r = e >> 4, q = e & 15;
                int v = tsm[r];
                int s = __ldg(&tokens[r * TSTEPS + t]);
                bool upd = (v != 0);
                int n = blk * 16 + q;

                float gi = bsm[q],      gf = bsm[16 + q];
                float gg = bsm[32 + q], go = bsm[48 + q];
#pragma unroll
                for (int b = 0; b < 4; ++b) {
                    const float* gb = gsm + b * (32 * GPITCH) + r * GPITCH;
                    gi += gb[q];      gf += gb[16 + q];
                    gg += gb[32 + q]; go += gb[48 + q];
                }
                float ia = fsig(gi), fa = fsig(gf);
                float ga = ftanh(gg), oa = fsig(go);
                size_t ci = (size_t)r * VOCAB + n;
                float cn = fa * g_c[ci] + ia * ga;
                float hn = oa * ftanh(cn);
                float h;
                if (upd) { g_c[ci] = cn; h = hn; g_h[ci] = h; }
                else     { h = g_h[ci]; }
                if (t < TSTEPS - 1)     // h cols of next step's A
                    g_Abf[t & 1][r * APITCH + EMB + n] = __float2bfloat16(h);
                float e2 = __expf(h);   // |h|<1: no max shift needed
                float Z = e2;
                float S = (n < s) ? e2 : ((n == s) ? 0.5f * e2 : 0.f);
#pragma unroll
                for (int o = 1; o < 16; o <<= 1) {
                    Z += __shfl_xor_sync(0xffffffffu, Z, o);
                    S += __shfl_xor_sync(0xffffffffu, S, o);
                }
                if (q == 0) {
                    g_partZ[t & 1][r * NBLK + blk] = Z;
                    g_partS[t & 1][r * NBLK + blk] = S;
                }
            }
            // emb cols of next step's A: this block owns cols 2*blk, 2*blk+1
            if (t < TSTEPS - 1 && tid < 64) {
                int rr = tid >> 1, col = blk * 2 + (tid & 1);
                int sv = __ldg(&tokens[rr * TSTEPS + t]);
                g_Abf[t & 1][rr * APITCH + col] =
                    __float2bfloat16(__ldg(&E[(size_t)sv * EMB + col]));
            }
        }

        grid_sync();   // A(t+1) + partials visible everywhere

        // ---------- finalize (blocks 0..31) while others start next GEMM ----
        if (blk < 32) {
            if (tid < NBLK) {      // warps 0..3 (full warps)
                float Z = g_partZ[t & 1][blk * NBLK + tid];
                float S = g_partS[t & 1][blk * NBLK + tid];
#pragma unroll
                for (int o = 16; o; o >>= 1) {
                    Z += __shfl_xor_sync(0xffffffffu, Z, o);
                    S += __shfl_xor_sync(0xffffffffu, S, o);
                }
                if (lane == 0) { redz[warp] = Z; reds[warp] = S; }
            }
            __syncthreads();
            float Zt = redz[0] + redz[1] + redz[2] + redz[3];
            float St = reds[0] + reds[1] + reds[2] + reds[3];
            if (tid < LAT)
                out[((size_t)blk * TSTEPS + t) * LAT + tid] = 3.0f * St / Zt;
            __syncthreads();   // redz reuse safety for next t
        }
    }
}

// ---------------- launch ----------------------------------------------------
extern "C" void kernel_launch(void* const* d_in, const int* in_sizes, int n_in,
                              void* d_out, int out_size) {
    const int* tokens = nullptr;
    const float *E = nullptr, *Wi = nullptr, *Wh = nullptr, *bias = nullptr;
    for (int i = 0; i < n_in; i++) {
        switch (in_sizes[i]) {
            case BATCH * TSTEPS:      tokens = (const int*)d_in[i];   break;
            case VOCAB * EMB:         E      = (const float*)d_in[i]; break;
            case EMB * 4 * VOCAB:     Wi     = (const float*)d_in[i]; break;
            case VOCAB * 4 * VOCAB:   Wh     = (const float*)d_in[i]; break;
            case 4 * VOCAB:           bias   = (const float*)d_in[i]; break;
        }
    }
    float* out = (float*)d_out;

    convert_kernel<<<CONV_BLOCKS, CONV_THREADS>>>(Wi, Wh, E, tokens, out);

    cudaFuncSetAttribute(persistent_kernel,
                         cudaFuncAttributeMaxDynamicSharedMemorySize, SMEM_BYTES);
    persistent_kernel<<<NBLK, THREADS, SMEM_BYTES>>>(tokens, bias, E, out);
}

// round 17
// speedup vs baseline: 1.6525x; 1.6525x over previous
#include <cuda_runtime.h>
#include <cuda_bf16.h>
#include <cstdint>
#include <cstddef>

#define VOCAB 2048
#define EMB 256
#define KTOT 2304          // EMB + VOCAB
#define NTOT 8192          // 4*VOCAB
#define BATCH 32
#define TSTEPS 8
#define LAT 128

#define NBLK 128           // persistent blocks; each owns 16 h-cols (x4 gates)
#define THREADS 288        // 8 compute warps (nq2 x kg4) + 1 producer warp
#define KTILE 192
#define NITER (KTOT / KTILE)   // 12
#define NITER1 2               // t==1: h==0; tiles 0,1 cover k<384 (h rows are 0)
#define STAGES 3
#define WPITCH 72              // bf16 elems per W row (64 + 8 pad)  [baked into gmem]
#define WSTAGE (KTILE * WPITCH)            // 13,824 elems
#define WTILE_BYTES (WSTAGE * 2)           // 27,648 B, contiguous in gmem
#define APITCH 2312            // bf16 elems per A row (2304 + 8 pad) [gmem AND smem]
#define AROW32 (32 * APITCH)               // 73,984 elems
#define AHALF_BYTES (16 * APITCH * 2)      // 73,984 B per row-half
#define GPITCH 66              // float pitch per gate-staging buffer (aliases Asm)
#define SMEM_BYTES ((AROW32 + STAGES * WSTAGE) * 2)        // 230,912 B

#define CONV_BLOCKS 256
#define CONV_THREADS 512

// ---------------- device scratch (no allocations allowed) -------------------
__device__ __align__(16) __nv_bfloat16 g_W[(size_t)NBLK * KTOT * WPITCH];  // 42.5MB
__device__ __align__(16) __nv_bfloat16 g_Abf[2][AROW32];   // ping-pong [emb|h] padded
__device__ float g_c[BATCH * VOCAB];
__device__ float g_h[BATCH * VOCAB];
__device__ float g_partZ[2][BATCH * NBLK];                  // ping-pong
__device__ float g_partS[2][BATCH * NBLK];
__device__ unsigned g_bar_cnt = 0;     // monotonic ticket counter (never reset)

// ---------------- helpers ----------------------------------------------------
__device__ __forceinline__ uint32_t smem_u32(const void* p) {
    return (uint32_t)__cvta_generic_to_shared(p);
}
__device__ __forceinline__ void mbar_init(uint32_t addr, uint32_t count) {
    asm volatile("mbarrier.init.shared.b64 [%0], %1;\n" :: "r"(addr), "r"(count) : "memory");
}
__device__ __forceinline__ void mbar_expect_tx(uint32_t addr, uint32_t bytes) {
    asm volatile("mbarrier.arrive.expect_tx.shared.b64 _, [%0], %1;\n"
                 :: "r"(addr), "r"(bytes) : "memory");
}
__device__ __forceinline__ void mbar_arrive(uint32_t addr) {
    asm volatile("mbarrier.arrive.shared.b64 _, [%0];\n" :: "r"(addr) : "memory");
}
__device__ __forceinline__ void bulk_g2s(uint32_t dst, const void* src,
                                         uint32_t bytes, uint32_t mbar) {
    asm volatile("cp.async.bulk.shared::cta.global.mbarrier::complete_tx::bytes "
                 "[%0], [%1], %2, [%3];\n"
                 :: "r"(dst), "l"(src), "r"(bytes), "r"(mbar) : "memory");
}
__device__ __forceinline__ void mbar_wait(uint32_t addr, uint32_t phase) {
    asm volatile("{\n\t.reg .pred p;\n"
                 "WAITLOOP%=:\n\t"
                 "mbarrier.try_wait.parity.shared.b64 p, [%0], %1;\n\t"
                 "@!p bra WAITLOOP%=;\n\t}"
                 :: "r"(addr), "r"(phase) : "memory");
}
__device__ __forceinline__ void ldsm_x4(uint32_t* r, uint32_t addr) {
    asm volatile("ldmatrix.sync.aligned.m8n8.x4.shared.b16 {%0,%1,%2,%3}, [%4];\n"
                 : "=r"(r[0]), "=r"(r[1]), "=r"(r[2]), "=r"(r[3]) : "r"(addr));
}
__device__ __forceinline__ void ldsm_x4_t(uint32_t* r, uint32_t addr) {
    asm volatile("ldmatrix.sync.aligned.m8n8.x4.trans.shared.b16 {%0,%1,%2,%3}, [%4];\n"
                 : "=r"(r[0]), "=r"(r[1]), "=r"(r[2]), "=r"(r[3]) : "r"(addr));
}
__device__ __forceinline__ void mma16816(float* d, const uint32_t* a, uint32_t b0, uint32_t b1) {
    asm volatile("mma.sync.aligned.m16n8k16.row.col.f32.bf16.bf16.f32 "
                 "{%0,%1,%2,%3}, {%4,%5,%6,%7}, {%8,%9}, {%0,%1,%2,%3};\n"
                 : "+f"(d[0]), "+f"(d[1]), "+f"(d[2]), "+f"(d[3])
                 : "r"(a[0]), "r"(a[1]), "r"(a[2]), "r"(a[3]), "r"(b0), "r"(b1));
}
__device__ __forceinline__ float fsig(float x)  { return __fdividef(1.f, 1.f + __expf(-x)); }
__device__ __forceinline__ float ftanh(float x) { return __fdividef(2.f, 1.f + __expf(-2.f * x)) - 1.f; }

__device__ __forceinline__ void cvt8(const float* __restrict__ src,
                                     __nv_bfloat16* __restrict__ dst) {
    float4 f0 = reinterpret_cast<const float4*>(src)[0];
    float4 f1 = reinterpret_cast<const float4*>(src)[1];
    __nv_bfloat162 b0 = __float22bfloat162_rn(make_float2(f0.x, f0.y));
    __nv_bfloat162 b1 = __float22bfloat162_rn(make_float2(f0.z, f0.w));
    __nv_bfloat162 b2 = __float22bfloat162_rn(make_float2(f1.x, f1.y));
    __nv_bfloat162 b3 = __float22bfloat162_rn(make_float2(f1.z, f1.w));
    uint4 pv;
    pv.x = *reinterpret_cast<unsigned*>(&b0);
    pv.y = *reinterpret_cast<unsigned*>(&b1);
    pv.z = *reinterpret_cast<unsigned*>(&b2);
    pv.w = *reinterpret_cast<unsigned*>(&b3);
    *reinterpret_cast<uint4*>(dst) = pv;
}

// Reset-free monotonic grid barrier (L2 atomics only; proven in R8).
__device__ __forceinline__ void grid_sync() {
    __syncthreads();
    if (threadIdx.x == 0) {
        __threadfence();                               // release prior stores
        unsigned ticket = atomicAdd(&g_bar_cnt, 1u);
        unsigned target = ticket - (ticket % NBLK) + NBLK;
        while (atomicAdd(&g_bar_cnt, 0u) < target) __nanosleep(64);
        __threadfence();                               // acquire others' stores
    }
    __syncthreads();
}

// ---------------- kernel 1: convert + repack (coalesced READS) --------------
__global__ __launch_bounds__(CONV_THREADS, 2) void convert_kernel(
    const float* __restrict__ Wi, const float* __restrict__ Wh,
    const float* __restrict__ E, const int* __restrict__ tokens,
    float* __restrict__ out)
{
    const int gid = blockIdx.x * CONV_THREADS + threadIdx.x;   // 0..131071
#pragma unroll
    for (int i = 0; i < 18; ++i) {                // 2,359,296 W chunks total
        int c = gid + i * (CONV_BLOCKS * CONV_THREADS);
        int k = c >> 10, cpos = c & 1023;
        int g = cpos >> 8, blkd = (cpos & 255) >> 1, half = cpos & 1;
        const float* src = ((k < EMB) ? (Wi + (size_t)k * NTOT)
                                      : (Wh + (size_t)(k - EMB) * NTOT)) + cpos * 8;
        cvt8(src, g_W + ((size_t)blkd * KTOT + k) * WPITCH + g * 16 + half * 8);
    }
    if (gid < BATCH * VOCAB) {                    // 65,536: fp32 state init
        g_c[gid] = 0.f;
        g_h[gid] = 0.f;
    }
    if (gid < AROW32) {                           // 73,984: A buffers for step 1
        int r = gid / APITCH, p = gid % APITCH;
        float v = 0.f;
        if (p < EMB) v = E[(size_t)tokens[r * TSTEPS] * EMB + p];   // token col 1
        g_Abf[0][gid] = __float2bfloat16(v);      // emb | h=0 | pad=0
        g_Abf[1][gid] = __float2bfloat16(0.f);
    }
    if (blockIdx.x == CONV_BLOCKS - 1) {          // out[:,0,:] = 0 (exact)
#pragma unroll
        for (int j = 0; j < 8; ++j) {
            int idx = threadIdx.x + j * CONV_THREADS;   // 0..4095
            out[((size_t)(idx >> 7) * TSTEPS) * LAT + (idx & 127)] = 0.f;
        }
    }
}

// ---------------- kernel 2: persistent step loop -----------------------------
// W stream: continuous global tile index j (74 total); mbarriers inited ONCE,
// phase (j/STAGES)&1. A: TWO large bulk TMAs per step (m_a phase = (t-1)&1),
// issued right after the grid barrier. NO small TMA slicing (R16 regression).
__global__ __launch_bounds__(THREADS, 1) void persistent_kernel(
    const int* __restrict__ tokens, const float* __restrict__ bias,
    const float* __restrict__ E, float* __restrict__ out)
{
    extern __shared__ __align__(16) char dynsmem[];
    __nv_bfloat16* Asm = reinterpret_cast<__nv_bfloat16*>(dynsmem);   // 32 x APITCH
    __nv_bfloat16* Wsm = Asm + AROW32;                                 // STAGES x WSTAGE
    float* gsm = reinterpret_cast<float*>(Asm);     // 4 x 32*GPITCH floats (alias)
    __shared__ float bsm[64];
    __shared__ float redz[4], reds[4];
    __shared__ int tsm[32];
    __shared__ __align__(8) uint64_t m_full[STAGES];
    __shared__ __align__(8) uint64_t m_empty[STAGES];
    __shared__ __align__(8) uint64_t m_a[2];

    const int blk  = blockIdx.x;
    const int tid  = threadIdx.x;
    const int lane = tid & 31, warp = tid >> 5;      // warps 0..8
    const int nq = warp & 1;          // n half: W cols nq*32..+32
    const int kg = warp >> 1;         // k-group 0..3: ks = kg*3 + {0,1,2}

    if (tid < 64)
        bsm[tid] = bias[(tid >> 4) * 2048 + blk * 16 + (tid & 15)];
    if (tid == 0) {                   // init ONCE; phases flow globally
#pragma unroll
        for (int s = 0; s < STAGES; ++s) {
            mbar_init(smem_u32(&m_full[s]), 1);
            mbar_init(smem_u32(&m_empty[s]), 8);    // 8 compute warps
        }
        mbar_init(smem_u32(&m_a[0]), 1);
        mbar_init(smem_u32(&m_a[1]), 1);
    }
    __syncthreads();

    const __nv_bfloat16* wblk = g_W + (size_t)blk * KTOT * WPITCH;
    int jglob = 0;   // global tile counter (74 total)

    for (int t = 1; t < TSTEPS; ++t) {
        const int nit = (t == 1) ? NITER1 : NITER;
        const int aph = (t - 1) & 1;   // m_a parity for this step

        if (tid < 32) tsm[tid] = tokens[tid * TSTEPS + (t - 1)];

        float acc[2][4][4];     // [mh][n8 chunk][frag]
#pragma unroll
        for (int i = 0; i < 2; i++)
#pragma unroll
            for (int j = 0; j < 4; j++)
#pragma unroll
                for (int f = 0; f < 4; f++) acc[i][j][f] = 0.f;

        if (warp == 8) {
            // ---------- producer warp: A (2 big TMAs) then W stream ----------
            if (lane == 0) {
                const __nv_bfloat16* abf = g_Abf[(t - 1) & 1];
#pragma unroll
                for (int hh = 0; hh < 2; ++hh) {
                    mbar_expect_tx(smem_u32(&m_a[hh]), AHALF_BYTES);
                    bulk_g2s(smem_u32(&Asm[hh * 16 * APITCH]),
                             abf + (size_t)hh * 16 * APITCH,
                             AHALF_BYTES, smem_u32(&m_a[hh]));
                }
                for (int it = 0; it < nit; ++it) {
                    const int j = jglob + it;
                    const int st = j % STAGES;
                    if (j >= STAGES)
                        mbar_wait(smem_u32(&m_empty[st]), ((j / STAGES) - 1) & 1);
                    mbar_expect_tx(smem_u32(&m_full[st]), WTILE_BYTES);
                    bulk_g2s(smem_u32(&Wsm[st * WSTAGE]),
                             wblk + (size_t)it * KTILE * WPITCH,
                             WTILE_BYTES, smem_u32(&m_full[st]));
                }
            }
        } else {
            // ---------- compute warps (8): M=32 x N=32 per warp --------------
            mbar_wait(smem_u32(&m_a[0]), aph);
            mbar_wait(smem_u32(&m_a[1]), aph);

            for (int it = 0; it < nit; ++it) {
                const int j = jglob + it;
                const int st = j % STAGES;
                mbar_wait(smem_u32(&m_full[st]), (j / STAGES) & 1);
                const __nv_bfloat16* ws = Wsm + st * WSTAGE;
                const int kbase = it * KTILE;
#pragma unroll
                for (int k2 = 0; k2 < 3; ++k2) {
                    const int ks = kg * 3 + k2;
                    const int acol = kbase + ks * 16 + (lane >> 4) * 8;
                    uint32_t a0[4], a1[4];
                    ldsm_x4(a0, smem_u32(&Asm[(lane & 15) * APITCH + acol]));
                    ldsm_x4(a1, smem_u32(&Asm[(16 + (lane & 15)) * APITCH + acol]));
                    const int krow = ks * 16 + (lane & 15);
#pragma unroll
                    for (int nsub = 0; nsub < 2; ++nsub) {
                        uint32_t bq[4];
                        int col = nq * 32 + nsub * 16 + (lane >> 4) * 8;
                        ldsm_x4_t(bq, smem_u32(&ws[krow * WPITCH + col]));
                        mma16816(acc[0][nsub * 2 + 0], a0, bq[0], bq[1]);
                        mma16816(acc[0][nsub * 2 + 1], a0, bq[2], bq[3]);
                        mma16816(acc[1][nsub * 2 + 0], a1, bq[0], bq[1]);
                        mma16816(acc[1][nsub * 2 + 1], a1, bq[2], bq[3]);
                    }
                }
                if (lane == 0) mbar_arrive(smem_u32(&m_empty[st]));
            }
        }
        jglob += nit;
        __syncthreads();        // [sync 1] all mainloop smem reads done (gsm alias)

        // ---------- epilogue: each warp stores to its own kg buffer ----------
        if (warp < 8) {
            float* gb = gsm + kg * (32 * GPITCH);
#pragma unroll
            for (int mhh = 0; mhh < 2; ++mhh)
#pragma unroll
                for (int nj = 0; nj < 4; ++nj) {
                    int row = mhh * 16 + (lane >> 2);
                    int col = nq * 32 + nj * 8 + (lane & 3) * 2;
                    *reinterpret_cast<float2*>(&gb[row * GPITCH + col]) =
                        make_float2(acc[mhh][nj][0], acc[mhh][nj][1]);
                    *reinterpret_cast<float2*>(&gb[(row + 8) * GPITCH + col]) =
                        make_float2(acc[mhh][nj][2], acc[mhh][nj][3]);
                }
        }
        __syncthreads();        // [sync 2] all 4 partial buffers ready

        // ---------- LSTM pointwise + partials + next-step A build ------------
        if (tid < 256) {
#pragma unroll
            for (int half = 0; half < 2; ++half) {
                int e = tid + half * 256;          // 0..511
                int r = e >> 4, q = e & 15;
                int v = tsm[r];
                int s = __ldg(&tokens[r * TSTEPS + t]);
                bool upd = (v != 0);
                int n = blk * 16 + q;

                float gi = bsm[q],      gf = bsm[16 + q];
                float gg = bsm[32 + q], go = bsm[48 + q];
#pragma unroll
                for (int b = 0; b < 4; ++b) {
                    const float* gb = gsm + b * (32 * GPITCH) + r * GPITCH;
                    gi += gb[q];      gf += gb[16 + q];
                    gg += gb[32 + q]; go += gb[48 + q];
                }
                float ia = fsig(gi), fa = fsig(gf);
                float ga = ftanh(gg), oa = fsig(go);
                size_t ci = (size_t)r * VOCAB + n;
                float cn = fa * g_c[ci] + ia * ga;
                float hn = oa * ftanh(cn);
                float h;
                if (upd) { g_c[ci] = cn; h = hn; g_h[ci] = h; }
                else     { h = g_h[ci]; }
                if (t < TSTEPS - 1)     // h cols of next step's A
                    g_Abf[t & 1][r * APITCH + EMB + n] = __float2bfloat16(h);
                float e2 = __expf(h);   // |h|<1: no max shift needed
                float Z = e2;
                float S = (n < s) ? e2 : ((n == s) ? 0.5f * e2 : 0.f);
#pragma unroll
                for (int o = 1; o < 16; o <<= 1) {
                    Z += __shfl_xor_sync(0xffffffffu, Z, o);
                    S += __shfl_xor_sync(0xffffffffu, S, o);
                }
                if (q == 0) {
                    g_partZ[t & 1][r * NBLK + blk] = Z;
                    g_partS[t & 1][r * NBLK + blk] = S;
                }
            }
            // emb cols of next step's A: this block owns cols 2*blk, 2*blk+1
            if (t < TSTEPS - 1 && tid < 64) {
                int rr = tid >> 1, col = blk * 2 + (tid & 1);
                int sv = __ldg(&tokens[rr * TSTEPS + t]);
                g_Abf[t & 1][rr * APITCH + col] =
                    __float2bfloat16(__ldg(&E[(size_t)sv * EMB + col]));
            }
        }

        grid_sync();   // A(t+1) + partials visible everywhere

        // ---------- finalize (blocks 0..31) while others start next GEMM ----
        if (blk < 32) {
            if (tid < NBLK) {      // warps 0..3 (full warps)
                float Z = g_partZ[t & 1][blk * NBLK + tid];
                float S = g_partS[t & 1][blk * NBLK + tid];
#pragma unroll
                for (int o = 16; o; o >>= 1) {
                    Z += __shfl_xor_sync(0xffffffffu, Z, o);
                    S += __shfl_xor_sync(0xffffffffu, S, o);
                }
                if (lane == 0) { redz[warp] = Z; reds[warp] = S; }
            }
            __syncthreads();
            float Zt = redz[0] + redz[1] + redz[2] + redz[3];
            float St = reds[0] + reds[1] + reds[2] + reds[3];
            if (tid < LAT)
                out[((size_t)blk * TSTEPS + t) * LAT + tid] = 3.0f * St / Zt;
            __syncthreads();   // redz reuse safety for next t
        }
    }
}

// ---------------- launch ----------------------------------------------------
extern "C" void kernel_launch(void* const* d_in, const int* in_sizes, int n_in,
                              void* d_out, int out_size) {
    const int* tokens = nullptr;
    const float *E = nullptr, *Wi = nullptr, *Wh = nullptr, *bias = nullptr;
    for (int i = 0; i < n_in; i++) {
        switch (in_sizes[i]) {
            case BATCH * TSTEPS:      tokens = (const int*)d_in[i];   break;
            case VOCAB * EMB:         E      = (const float*)d_in[i]; break;
            case EMB * 4 * VOCAB:     Wi     = (const float*)d_in[i]; break;
            case VOCAB * 4 * VOCAB:   Wh     = (const float*)d_in[i]; break;
            case 4 * VOCAB:           bias   = (const float*)d_in[i]; break;
        }
    }
    float* out = (float*)d_out;

    convert_kernel<<<CONV_BLOCKS, CONV_THREADS>>>(Wi, Wh, E, tokens, out);

    cudaFuncSetAttribute(persistent_kernel,
                         cudaFuncAttributeMaxDynamicSharedMemorySize, SMEM_BYTES);
    persistent_kernel<<<NBLK, THREADS, SMEM_BYTES>>>(tokens, bias, E, out);
}